// round 4
// baseline (speedup 1.0000x reference)
#include <cuda_runtime.h>

#define NB      100000
#define NNODES  600000
#define NODE_F  128
#define EDGE_F  32
#define OUT_F   128
#define SUM_F   160     // NODE_F + EDGE_F
#define TILE    64      // nodes per block
#define NWARPS  8
#define MPW     8       // nodes per warp (NWARPS*MPW == TILE)

// Scratch for BN statistics (device globals — no allocation allowed)
__device__ float g_sum[OUT_F];
__device__ float g_sq[OUT_F];
__device__ float g_mean[OUT_F];
__device__ float g_inv[OUT_F];

struct Params {
    const float* node_repr;
    const float* edge_repr;
    const float* W_self;
    const float* bias;
    const float* Wd[5];
    const int*   nidx[5];
    const int*   eidx[5];
    float*       out;
};

__global__ void zero_stats_kernel() {
    int t = threadIdx.x;
    if (t < OUT_F) { g_sum[t] = 0.f; g_sq[t] = 0.f; }
}

#define FMA4(A, S, W) do { \
    (A).x = fmaf((S), (W).x, (A).x); \
    (A).y = fmaf((S), (W).y, (A).y); \
    (A).z = fmaf((S), (W).z, (A).z); \
    (A).w = fmaf((S), (W).w, (A).w); } while (0)

extern __shared__ float smem[];

// One block = 64 nodes of one degree bucket.
// Smem: Wsm[160][128] (80KB, used as [128][128] in phase A), Xsm[64][160] (40KB),
//       Rsum[8][128] + Rsq[8][128] (8KB)  => 128KB total.
__global__ __launch_bounds__(256, 1)
void fused_kernel(Params p) {
    float* Wsm  = smem;                          // SUM_F * OUT_F
    float* Xsm  = Wsm + SUM_F * OUT_F;           // TILE * SUM_F
    float* Rsum = Xsm + TILE * SUM_F;            // NWARPS * OUT_F
    float* Rsq  = Rsum + NWARPS * OUT_F;         // NWARPS * OUT_F

    const int bucket = blockIdx.y;               // 0..5 (== degree)
    const int base   = blockIdx.x * TILE;        // bucket-local node offset
    const int tid    = threadIdx.x;
    const int w      = tid >> 5;
    const int lane   = tid & 31;
    const int col    = lane * 4;                 // this lane owns output cols [col, col+4)
    const int m0     = w * MPW;

    // ---- load W_self (128x128) into smem, coalesced float4 ----
    for (int i = tid * 4; i < NODE_F * OUT_F; i += 256 * 4)
        *(float4*)(Wsm + i) = *(const float4*)(p.W_self + i);

    // ---- load self inputs: Xsm[i][0..127] = node_repr[bucket*NB + base + i] ----
    for (int idx = tid; idx < TILE * (NODE_F / 4); idx += 256) {
        int i  = idx >> 5;             // node in tile
        int c4 = (idx & 31) * 4;
        int ib = base + i; if (ib >= NB) ib = NB - 1;       // clamp tail
        size_t node = (size_t)bucket * NB + ib;
        *(float4*)(Xsm + i * SUM_F + c4) =
            *(const float4*)(p.node_repr + node * NODE_F + c4);
    }
    __syncthreads();

    float4 bias4 = *(const float4*)(p.bias + col);
    float4 acc[MPW];
#pragma unroll
    for (int m = 0; m < MPW; m++) acc[m] = bias4;

    // ---- Phase A: self part, k = 0..127 ----
#pragma unroll 2
    for (int k4 = 0; k4 < NODE_F / 4; k4++) {
        float4 w0 = *(float4*)(Wsm + (k4 * 4 + 0) * OUT_F + col);
        float4 w1 = *(float4*)(Wsm + (k4 * 4 + 1) * OUT_F + col);
        float4 w2 = *(float4*)(Wsm + (k4 * 4 + 2) * OUT_F + col);
        float4 w3 = *(float4*)(Wsm + (k4 * 4 + 3) * OUT_F + col);
#pragma unroll
        for (int m = 0; m < MPW; m++) {
            float4 xq = *(float4*)(Xsm + (m0 + m) * SUM_F + k4 * 4);
            FMA4(acc[m], xq.x, w0);
            FMA4(acc[m], xq.y, w1);
            FMA4(acc[m], xq.z, w2);
            FMA4(acc[m], xq.w, w3);
        }
    }

    // ---- Phase B: neighbor part (degree >= 1) ----
    if (bucket > 0) {
        const int    deg  = bucket;
        const float* Wd   = p.Wd[deg - 1];
        const int*   nidx = p.nidx[deg - 1];
        const int*   eidx = p.eidx[deg - 1];

        __syncthreads();   // everyone done reading phase-A Wsm/Xsm

        // load W_d (160x128)
        for (int i = tid * 4; i < SUM_F * OUT_F; i += 256 * 4)
            *(float4*)(Wsm + i) = *(const float4*)(Wd + i);

        // gather + sum neighbors into this warp's Xsm rows
        for (int m = 0; m < MPW; m++) {
            int ib = base + m0 + m; if (ib >= NB) ib = NB - 1;
            float4 ns = {0.f, 0.f, 0.f, 0.f};
            for (int j = 0; j < deg; j++) {
                int nid = nidx[ib * deg + j];
                float4 v = *(const float4*)(p.node_repr + (size_t)nid * NODE_F + col);
                ns.x += v.x; ns.y += v.y; ns.z += v.z; ns.w += v.w;
            }
            *(float4*)(Xsm + (m0 + m) * SUM_F + col) = ns;
            if (lane < EDGE_F / 4) {
                float4 es = {0.f, 0.f, 0.f, 0.f};
                for (int j = 0; j < deg; j++) {
                    int eid = eidx[ib * deg + j];
                    float4 v = *(const float4*)(p.edge_repr + (size_t)eid * EDGE_F + col);
                    es.x += v.x; es.y += v.y; es.z += v.z; es.w += v.w;
                }
                *(float4*)(Xsm + (m0 + m) * SUM_F + NODE_F + col) = es;
            }
        }
        __syncthreads();

        // compute k = 0..159
#pragma unroll 2
        for (int k4 = 0; k4 < SUM_F / 4; k4++) {
            float4 w0 = *(float4*)(Wsm + (k4 * 4 + 0) * OUT_F + col);
            float4 w1 = *(float4*)(Wsm + (k4 * 4 + 1) * OUT_F + col);
            float4 w2 = *(float4*)(Wsm + (k4 * 4 + 2) * OUT_F + col);
            float4 w3 = *(float4*)(Wsm + (k4 * 4 + 3) * OUT_F + col);
#pragma unroll
            for (int m = 0; m < MPW; m++) {
                float4 xq = *(float4*)(Xsm + (m0 + m) * SUM_F + k4 * 4);
                FMA4(acc[m], xq.x, w0);
                FMA4(acc[m], xq.y, w1);
                FMA4(acc[m], xq.z, w2);
                FMA4(acc[m], xq.w, w3);
            }
        }
    }

    // ---- store a into d_out (pre-BN) + per-block column partials ----
    const int nvalid = (NB - base < TILE) ? (NB - base) : TILE;
    float4 ps = {0.f, 0.f, 0.f, 0.f};
    float4 pq = {0.f, 0.f, 0.f, 0.f};
#pragma unroll
    for (int m = 0; m < MPW; m++) {
        int il = m0 + m;
        if (il < nvalid) {
            size_t node = (size_t)bucket * NB + base + il;
            float4 v = acc[m];
            *(float4*)(p.out + node * OUT_F + col) = v;
            ps.x += v.x; ps.y += v.y; ps.z += v.z; ps.w += v.w;
            pq.x += v.x * v.x; pq.y += v.y * v.y;
            pq.z += v.z * v.z; pq.w += v.w * v.w;
        }
    }
    *(float4*)(Rsum + w * OUT_F + col) = ps;
    *(float4*)(Rsq  + w * OUT_F + col) = pq;
    __syncthreads();
    if (tid < OUT_F) {
        float s = 0.f, q = 0.f;
#pragma unroll
        for (int ww = 0; ww < NWARPS; ww++) {
            s += Rsum[ww * OUT_F + tid];
            q += Rsq[ww * OUT_F + tid];
        }
        atomicAdd(&g_sum[tid], s);
        atomicAdd(&g_sq[tid], q);
    }
}

__global__ void stats_kernel() {
    int t = threadIdx.x;
    if (t < OUT_F) {
        float mean = g_sum[t] * (1.0f / (float)NNODES);
        float var  = g_sq[t] * (1.0f / (float)NNODES) - mean * mean;
        g_mean[t] = mean;
        g_inv[t]  = rsqrtf(var + 1e-5f);
    }
}

// In-place BN (affine-free) + ReLU over d_out. One float4 per thread.
__global__ __launch_bounds__(256) void norm_relu_kernel(float* out) {
    size_t i = (size_t)blockIdx.x * blockDim.x + threadIdx.x;  // float4 index
    int col = (int)(i & (OUT_F / 4 - 1)) * 4;
    float4 mv = *(const float4*)(g_mean + col);
    float4 iv = *(const float4*)(g_inv + col);
    float4 v  = *(float4*)(out + i * 4);
    v.x = fmaxf(0.f, (v.x - mv.x) * iv.x);
    v.y = fmaxf(0.f, (v.y - mv.y) * iv.y);
    v.z = fmaxf(0.f, (v.z - mv.z) * iv.z);
    v.w = fmaxf(0.f, (v.w - mv.w) * iv.w);
    *(float4*)(out + i * 4) = v;
}

extern "C" void kernel_launch(void* const* d_in, const int* in_sizes, int n_in,
                              void* d_out, int out_size) {
    Params p;
    p.node_repr = (const float*)d_in[0];
    p.edge_repr = (const float*)d_in[1];
    p.W_self    = (const float*)d_in[2];
    p.bias      = (const float*)d_in[3];
    for (int d = 0; d < 5; d++) {
        p.Wd[d]   = (const float*)d_in[4 + 3 * d];
        p.nidx[d] = (const int*)  d_in[5 + 3 * d];
        p.eidx[d] = (const int*)  d_in[6 + 3 * d];
    }
    p.out = (float*)d_out;

    const size_t smem_bytes =
        (SUM_F * OUT_F + TILE * SUM_F + 2 * NWARPS * OUT_F) * sizeof(float); // 131072
    cudaFuncSetAttribute(fused_kernel,
                         cudaFuncAttributeMaxDynamicSharedMemorySize,
                         (int)smem_bytes);

    zero_stats_kernel<<<1, 128>>>();

    dim3 grid((NB + TILE - 1) / TILE, 6);
    fused_kernel<<<grid, 256, smem_bytes>>>(p);

    stats_kernel<<<1, 128>>>();

    const size_t n4 = (size_t)NNODES * OUT_F / 4;   // 19,200,000
    norm_relu_kernel<<<(unsigned)(n4 / 256), 256>>>((float*)d_out);
}